// round 3
// baseline (speedup 1.0000x reference)
#include <cuda_runtime.h>
#include <cuda_bf16.h>
#include <cstdint>

#define C_   64
#define T_   262144
#define NS   8          // biquad stages
#define SD   16         // state dim (2 per stage, DF2T)
#define L_   128        // samples per block
#define B_   (T_ / L_)  // 2048 blocks per channel
#define G_   32         // blocks per super-block
#define S_   (B_ / G_)  // 64 super-blocks per channel

// Scratch (static device globals; no allocation allowed)
__device__ float g_chain[8 * 256];        // A^(2^k), k=0..7  (A^128 at k=7)
__device__ float g_c[16];                 // output row vector c
__device__ float g_H[L_ * 16];            // H[tau][j] = (c^T A^tau)_j
__device__ float g_Mpow[(G_ + 1) * 256];  // M^r, r=0..32, M = A^L
__device__ float g_d[(size_t)C_ * B_ * SD];     // zero-entry exit states per block
__device__ float g_pref[(size_t)C_ * B_ * SD];  // local prefixes -> global entry states
__device__ float g_agg[(size_t)C_ * S_ * SD];   // super-block aggregates
__device__ float g_SE[(size_t)C_ * S_ * SD];    // super-block entry states

#define SHFL16(v, j) __shfl_sync(0xffffffffu, (v), (j), 16)

// ---------------------------------------------------------------------------
// K0: build state-space (A, c), power chain, H table, M powers. One CTA.
// ---------------------------------------------------------------------------
__global__ void k0_build(const float* __restrict__ sos) {
    __shared__ float sX[256];
    __shared__ float sM[256];
    const int tid = threadIdx.x;
    const int i = tid >> 4, j = tid & 15;

    // --- symbolic build of A (16x16) and c (16): thread 'tid' owns coefficient
    // column tid (0..15 = states, 16 = x). DF2T per stage:
    //   y = b0*u + w1 ; w1' = b1*u - a1*y + w2 ; w2' = b2*u - a2*y
    if (tid < 17) {
        float u = (tid == 16) ? 1.f : 0.f;
        for (int s = 0; s < NS; s++) {
            float B0 = sos[s * 6 + 0], B1 = sos[s * 6 + 1], B2 = sos[s * 6 + 2];
            float A1 = sos[s * 6 + 4], A2 = sos[s * 6 + 5];
            float y  = B0 * u + ((tid == 2 * s) ? 1.f : 0.f);
            float r1 = B1 * u - A1 * y + ((tid == 2 * s + 1) ? 1.f : 0.f);
            float r2 = B2 * u - A2 * y;
            if (tid < 16) {
                g_chain[(2 * s) * 16 + tid]     = r1;  // row 2s of A
                g_chain[(2 * s + 1) * 16 + tid] = r2;  // row 2s+1 of A
            }
            u = y;
        }
        if (tid < 16) { g_c[tid] = u; g_H[tid] = u; }  // H[0] = c
    }
    __syncthreads();

    // --- squaring chain: chain[k] = chain[k-1]^2  (k = 1..7, A^2 .. A^128)
    for (int k = 1; k <= 7; k++) {
        sX[tid] = g_chain[(k - 1) * 256 + tid];
        __syncthreads();
        float acc = 0.f;
#pragma unroll
        for (int m = 0; m < 16; m++) acc = fmaf(sX[i * 16 + m], sX[m * 16 + j], acc);
        g_chain[k * 256 + tid] = acc;
        __syncthreads();
    }

    // --- H doubling: for k=0..6, H[t] = H[t-2^k] * A^(2^k), t in [2^k, 2^(k+1))
    for (int k = 0; k <= 6; k++) {
        const int m = 1 << k;
        sX[tid] = g_chain[k * 256 + tid];
        __syncthreads();
        for (int idx = tid; idx < m * 16; idx += 256) {
            const int row = idx >> 4, col = idx & 15;
            float acc = 0.f;
#pragma unroll
            for (int p = 0; p < 16; p++)
                acc = fmaf(g_H[row * 16 + p], sX[p * 16 + col], acc);
            g_H[(m + row) * 16 + col] = acc;
        }
        __syncthreads();
    }

    // --- Mpow[0] = I, Mpow[1] = A^128, Mpow[r] = Mpow[r-1] * M
    g_Mpow[tid] = (i == j) ? 1.f : 0.f;
    const float Mv = g_chain[7 * 256 + tid];
    g_Mpow[256 + tid] = Mv;
    sM[tid] = Mv;
    __syncthreads();
    for (int r = 2; r <= G_; r++) {
        float acc = 0.f;
#pragma unroll
        for (int m = 0; m < 16; m++)
            acc = fmaf(g_Mpow[(r - 1) * 256 + i * 16 + m], sM[m * 16 + j], acc);
        g_Mpow[r * 256 + tid] = acc;
        __syncthreads();
    }
}

// ---------------------------------------------------------------------------
// K1: zero-entry-state cascade per (channel, block). Writes z to out and exit
// state to g_d.
// ---------------------------------------------------------------------------
__device__ __forceinline__ float cascade_step(
    float u, float* w1, float* w2,
    const float* cb0, const float* cb1, const float* cb2,
    const float* na1, const float* na2) {
#pragma unroll
    for (int s = 0; s < NS; s++) {
        float y = fmaf(cb0[s], u, w1[s]);
        w1[s] = fmaf(cb1[s], u, fmaf(na1[s], y, w2[s]));
        w2[s] = fmaf(cb2[s], u, na2[s] * y);
        u = y;
    }
    return u;
}

__global__ void __launch_bounds__(128) k1_blocks(
    const float* __restrict__ x, const float* __restrict__ sos,
    float* __restrict__ out) {
    const int tid = blockIdx.x * 128 + threadIdx.x;  // 0 .. C_*B_-1
    const int c = tid >> 11;   // / B_
    const int b = tid & (B_ - 1);

    float cb0[NS], cb1[NS], cb2[NS], na1[NS], na2[NS];
#pragma unroll
    for (int s = 0; s < NS; s++) {
        cb0[s] = sos[s * 6 + 0];
        cb1[s] = sos[s * 6 + 1];
        cb2[s] = sos[s * 6 + 2];
        na1[s] = -sos[s * 6 + 4];
        na2[s] = -sos[s * 6 + 5];
    }
    float w1[NS], w2[NS];
#pragma unroll
    for (int s = 0; s < NS; s++) { w1[s] = 0.f; w2[s] = 0.f; }

    const size_t base = (size_t)c * T_ + (size_t)b * L_;
    const float4* xp = reinterpret_cast<const float4*>(x + base);
    float4* op = reinterpret_cast<float4*>(out + base);

#pragma unroll 1
    for (int q = 0; q < L_ / 4; q++) {
        float4 v = xp[q];
        v.x = cascade_step(v.x, w1, w2, cb0, cb1, cb2, na1, na2);
        v.y = cascade_step(v.y, w1, w2, cb0, cb1, cb2, na1, na2);
        v.z = cascade_step(v.z, w1, w2, cb0, cb1, cb2, na1, na2);
        v.w = cascade_step(v.w, w1, w2, cb0, cb1, cb2, na1, na2);
        op[q] = v;
    }

    float* dp = g_d + (size_t)tid * SD;
#pragma unroll
    for (int s = 0; s < NS; s++) { dp[2 * s] = w1[s]; dp[2 * s + 1] = w2[s]; }
}

// ---------------------------------------------------------------------------
// K2a: local affine scan inside each super-block (G_ steps). Lane = component.
// ---------------------------------------------------------------------------
__global__ void k2a_local(void) {
    const int tid = blockIdx.x * blockDim.x + threadIdx.x;  // C_*S_*16
    const int comp = tid & 15;
    const int pair = tid >> 4;          // c*S_ + g
    const int g = pair & (S_ - 1);
    const int c = pair >> 6;            // S_ = 64
    float Mrow[16];
#pragma unroll
    for (int j = 0; j < 16; j++) Mrow[j] = g_Mpow[256 + comp * 16 + j];  // M

    float p = 0.f;
    const int baseBlk = c * B_ + g * G_;
    for (int i2 = 0; i2 < G_; i2++) {
        g_pref[(size_t)(baseBlk + i2) * SD + comp] = p;
        float acc = g_d[(size_t)(baseBlk + i2) * SD + comp];
#pragma unroll
        for (int j = 0; j < 16; j++) acc = fmaf(Mrow[j], SHFL16(p, j), acc);
        p = acc;
    }
    g_agg[(size_t)pair * SD + comp] = p;
}

// ---------------------------------------------------------------------------
// K2b: scan over super-blocks (S_ steps) per channel with M^G.
// ---------------------------------------------------------------------------
__global__ void k2b_super(void) {
    const int tid = blockIdx.x * blockDim.x + threadIdx.x;  // C_*16 = 1024
    const int comp = tid & 15;
    const int c = tid >> 4;
    float Mrow[16];
#pragma unroll
    for (int j = 0; j < 16; j++) Mrow[j] = g_Mpow[G_ * 256 + comp * 16 + j];  // M^G

    float sv = 0.f;
    for (int g = 0; g < S_; g++) {
        g_SE[(size_t)(c * S_ + g) * SD + comp] = sv;
        float acc = g_agg[(size_t)(c * S_ + g) * SD + comp];
#pragma unroll
        for (int j = 0; j < 16; j++) acc = fmaf(Mrow[j], SHFL16(sv, j), acc);
        sv = acc;
    }
}

// ---------------------------------------------------------------------------
// K2c: global entry state per block: E = M^(b%G) * SE[g] + local_prefix.
// ---------------------------------------------------------------------------
__global__ void k2c_fixup(void) {
    const size_t tid = (size_t)blockIdx.x * blockDim.x + threadIdx.x;  // C_*B_*16
    const int comp = (int)(tid & 15);
    const size_t idx = tid >> 4;        // c*B_ + b
    const int b = (int)(idx & (B_ - 1));
    const int c = (int)(idx >> 11);
    const int g = b >> 5;               // / G_
    const int i2 = b & (G_ - 1);

    float acc = g_pref[tid];
    const float* Mr = g_Mpow + i2 * 256 + comp * 16;
    const float* se = g_SE + (size_t)(c * S_ + g) * SD;
#pragma unroll
    for (int j = 0; j < 16; j++) acc = fmaf(Mr[j], se[j], acc);
    g_pref[tid] = acc;  // in-place: each thread touches only its own slot
}

// ---------------------------------------------------------------------------
// K3: out[c][b*L+tau] += H[tau] . E[c][b]   (float4 per thread)
// ---------------------------------------------------------------------------
__global__ void __launch_bounds__(256) k3_correct(float* __restrict__ out) {
    const size_t q = (size_t)blockIdx.x * 256 + threadIdx.x;  // < C_*T_/4
    const size_t blk = q >> 5;          // (c*T + t)/L = c*B_ + b
    const int tau = (int)(q & 31) << 2; // sample offset within block (0..124)

    const float4* s04 = reinterpret_cast<const float4*>(g_pref + blk * SD);
    float s0r[16];
#pragma unroll
    for (int jj = 0; jj < 4; jj++) {
        float4 v = s04[jj];
        s0r[4 * jj + 0] = v.x; s0r[4 * jj + 1] = v.y;
        s0r[4 * jj + 2] = v.z; s0r[4 * jj + 3] = v.w;
    }

    float4* out4 = reinterpret_cast<float4*>(out);
    float4 a = out4[q];
    float accs[4] = {a.x, a.y, a.z, a.w};
#pragma unroll
    for (int r = 0; r < 4; r++) {
        const float4* hr = reinterpret_cast<const float4*>(g_H + (tau + r) * 16);
#pragma unroll
        for (int jj = 0; jj < 4; jj++) {
            float4 h = hr[jj];
            accs[r] = fmaf(h.x, s0r[4 * jj + 0], accs[r]);
            accs[r] = fmaf(h.y, s0r[4 * jj + 1], accs[r]);
            accs[r] = fmaf(h.z, s0r[4 * jj + 2], accs[r]);
            accs[r] = fmaf(h.w, s0r[4 * jj + 3], accs[r]);
        }
    }
    out4[q] = make_float4(accs[0], accs[1], accs[2], accs[3]);
}

// ---------------------------------------------------------------------------
extern "C" void kernel_launch(void* const* d_in, const int* in_sizes, int n_in,
                              void* d_out, int out_size) {
    const float* x   = (const float*)d_in[0];   // [C, T]
    const float* sos = (const float*)d_in[1];   // [8, 6]
    float* out = (float*)d_out;                 // [C, T]

    k0_build<<<1, 256>>>(sos);
    k1_blocks<<<(C_ * B_) / 128, 128>>>(x, sos, out);
    k2a_local<<<(C_ * S_ * SD) / 128, 128>>>();
    k2b_super<<<(C_ * SD) / 128, 128>>>();
    k2c_fixup<<<(C_ * B_ * SD) / 128, 128>>>();
    k3_correct<<<(C_ * T_ / 4) / 256, 256>>>(out);
}

// round 5
// speedup vs baseline: 1.2597x; 1.2597x over previous
#include <cuda_runtime.h>
#include <cuda_bf16.h>
#include <cstdint>

#define C_   64
#define T_   262144
#define NS   8          // biquad stages
#define SD   16         // state dim (2 per stage, DF2T)
#define L_   128        // samples per block
#define B_   (T_ / L_)  // 2048 blocks per channel
#define NG   64         // groups per channel in scan
#define NSEQ (B_ / NG)  // 32 blocks scanned sequentially per group

// Scratch (static device globals; no allocation allowed)
__device__ float g_M[256];                      // A^L  (block step matrix)
__device__ float g_L2M[256];                    // M^NSEQ (level-2 step matrix)
__device__ float g_H[L_ * 16];                  // H[tau][j] = (c^T A^tau)_j
__device__ float g_d[(size_t)C_ * B_ * SD];     // zero-entry exit states per block
__device__ float g_pref[(size_t)C_ * B_ * SD];  // global entry states per block

#define SHFL16(v, j) __shfl_sync(0xffffffffu, (v), (j), 16)

// ---------------------------------------------------------------------------
// K0: build state-space (A, c), H table (doubling), M = A^128, L2M = M^32.
// Entirely in shared memory. One CTA of 256 threads.
// ---------------------------------------------------------------------------
__global__ void k0_build(const float* __restrict__ sos) {
    __shared__ float sA[256];
    __shared__ float sB[256];
    __shared__ float sH[L_ * 16];
    const int tid = threadIdx.x;
    const int i = tid >> 4, j = tid & 15;

    // symbolic build of A (16x16, row-major) and c. Thread tid = input column
    // (0..15 = states, 16 = x). DF2T per stage:
    //   y = b0*u + w1 ; w1' = b1*u - a1*y + w2 ; w2' = b2*u - a2*y
    if (tid < 17) {
        float u = (tid == 16) ? 1.f : 0.f;
        for (int s = 0; s < NS; s++) {
            float B0 = sos[s * 6 + 0], B1 = sos[s * 6 + 1], B2 = sos[s * 6 + 2];
            float A1 = sos[s * 6 + 4], A2 = sos[s * 6 + 5];
            float y  = B0 * u + ((tid == 2 * s) ? 1.f : 0.f);
            float r1 = B1 * u - A1 * y + ((tid == 2 * s + 1) ? 1.f : 0.f);
            float r2 = B2 * u - A2 * y;
            if (tid < 16) {
                sA[(2 * s) * 16 + tid]     = r1;
                sA[(2 * s + 1) * 16 + tid] = r2;
            }
            u = y;
        }
        if (tid < 16) sH[tid] = u;  // H[0] = c
    }
    __syncthreads();

    // interleaved: at loop top sA = A^(2^k). Double H, then square sA.
    for (int k = 0; k <= 6; k++) {
        const int m = 1 << k;
        // H[m + t] = H[t] * sA   for t in [0, m)  (reads rows <m, writes >=m)
        for (int idx = tid; idx < m * 16; idx += 256) {
            const int row = idx >> 4, col = idx & 15;
            float acc = 0.f;
#pragma unroll
            for (int p = 0; p < 16; p++)
                acc = fmaf(sH[row * 16 + p], sA[p * 16 + col], acc);
            sH[(m + row) * 16 + col] = acc;
        }
        __syncthreads();
        // sA = sA * sA
        {
            float acc = 0.f;
#pragma unroll
            for (int p = 0; p < 16; p++)
                acc = fmaf(sA[i * 16 + p], sA[p * 16 + j], acc);
            __syncthreads();
            sB[tid] = acc;
            __syncthreads();
            sA[tid] = sB[tid];
            __syncthreads();
        }
    }
    // sA = A^128 = M
    g_M[tid] = sA[tid];

    // 5 more squarings: M^2 .. M^32
    for (int k = 0; k < 5; k++) {
        float acc = 0.f;
#pragma unroll
        for (int p = 0; p < 16; p++)
            acc = fmaf(sA[i * 16 + p], sA[p * 16 + j], acc);
        __syncthreads();
        sB[tid] = acc;
        __syncthreads();
        sA[tid] = sB[tid];
        __syncthreads();
    }
    g_L2M[tid] = sA[tid];

    for (int idx = tid; idx < L_ * 16; idx += 256) g_H[idx] = sH[idx];
}

// ---------------------------------------------------------------------------
// K1: zero-entry-state cascade per (channel, block), smem-staged coalesced IO.
// CTA = 128 threads = 128 consecutive blocks of one channel. 4 tiles of 32
// samples, sample-major smem layout (row stride 129 floats, conflict-free).
// ---------------------------------------------------------------------------
__global__ void __launch_bounds__(128) k1_blocks(
    const float* __restrict__ x, const float* __restrict__ sos,
    float* __restrict__ out) {
    __shared__ float tile[32 * 129];
    const int tid = threadIdx.x;
    const int c = blockIdx.x >> 4;            // 16 CTAs per channel
    const int blk0 = (blockIdx.x & 15) * 128; // first block of this CTA

    float cb0[NS], cb1[NS], cb2[NS], na1[NS], na2[NS];
#pragma unroll
    for (int s = 0; s < NS; s++) {
        cb0[s] = sos[s * 6 + 0];
        cb1[s] = sos[s * 6 + 1];
        cb2[s] = sos[s * 6 + 2];
        na1[s] = -sos[s * 6 + 4];
        na2[s] = -sos[s * 6 + 5];
    }
    float w1[NS], w2[NS];
#pragma unroll
    for (int s = 0; s < NS; s++) { w1[s] = 0.f; w2[s] = 0.f; }

    const size_t base4 = (size_t)c * (T_ / 4) + (size_t)blk0 * (L_ / 4);
    const float4* xp4 = reinterpret_cast<const float4*>(x) + base4;
    float4* op4 = reinterpret_cast<float4*>(out) + base4;

    for (int t = 0; t < 4; t++) {
        // load: 1024 f4 per tile, coalesced; scatter into sample-major smem
#pragma unroll
        for (int it = 0; it < 8; it++) {
            const int idx = it * 128 + tid;     // 0..1023
            const int bl = idx >> 3;            // local block 0..127
            const int k = idx & 7;              // f4 within tile row of block
            float4 v = xp4[(size_t)bl * 32 + t * 8 + k];
            tile[(4 * k + 0) * 129 + bl] = v.x;
            tile[(4 * k + 1) * 129 + bl] = v.y;
            tile[(4 * k + 2) * 129 + bl] = v.z;
            tile[(4 * k + 3) * 129 + bl] = v.w;
        }
        __syncthreads();
        // compute in place: thread tid = its block's column
#pragma unroll
        for (int s2 = 0; s2 < 32; s2++) {
            float u = tile[s2 * 129 + tid];
#pragma unroll
            for (int s = 0; s < NS; s++) {
                float y = fmaf(cb0[s], u, w1[s]);
                w1[s] = fmaf(cb1[s], u, fmaf(na1[s], y, w2[s]));
                w2[s] = fmaf(cb2[s], u, na2[s] * y);
                u = y;
            }
            tile[s2 * 129 + tid] = u;
        }
        __syncthreads();
        // store: mirror of load, coalesced
#pragma unroll
        for (int it = 0; it < 8; it++) {
            const int idx = it * 128 + tid;
            const int bl = idx >> 3;
            const int k = idx & 7;
            float4 v;
            v.x = tile[(4 * k + 0) * 129 + bl];
            v.y = tile[(4 * k + 1) * 129 + bl];
            v.z = tile[(4 * k + 2) * 129 + bl];
            v.w = tile[(4 * k + 3) * 129 + bl];
            op4[(size_t)bl * 32 + t * 8 + k] = v;
        }
        __syncthreads();
    }

    float* dp = g_d + ((size_t)c * B_ + blk0 + tid) * SD;
#pragma unroll
    for (int s = 0; s < NS; s++) { dp[2 * s] = w1[s]; dp[2 * s + 1] = w2[s]; }
}

// ---------------------------------------------------------------------------
// K2: fused inter-block scan. One CTA per channel, 1024 threads = 64 groups
// of 16 lanes. scan1 (32 steps) -> level-2 scan over 64 aggregates (warp 0,
// M^32) -> rescan seeded with group entry states, writing E to g_pref.
// ---------------------------------------------------------------------------
__device__ __forceinline__ float mv16(const float* Mr, float p) {
    float a0 = 0.f, a1 = 0.f, a2 = 0.f, a3 = 0.f;
#pragma unroll
    for (int j = 0; j < 4; j++)  a0 = fmaf(Mr[j],      SHFL16(p, j),      a0);
#pragma unroll
    for (int j = 0; j < 4; j++)  a1 = fmaf(Mr[j + 4],  SHFL16(p, j + 4),  a1);
#pragma unroll
    for (int j = 0; j < 4; j++)  a2 = fmaf(Mr[j + 8],  SHFL16(p, j + 8),  a2);
#pragma unroll
    for (int j = 0; j < 4; j++)  a3 = fmaf(Mr[j + 12], SHFL16(p, j + 12), a3);
    return (a0 + a1) + (a2 + a3);
}

__global__ void __launch_bounds__(1024) k2_scan(void) {
    __shared__ float sAgg[NG * 16];
    __shared__ float sGE[NG * 16];
    const int tid = threadIdx.x;
    const int lane = tid & 15;
    const int grp = tid >> 4;           // 0..63
    const int c = blockIdx.x;

    float Mrow[16];
#pragma unroll
    for (int j = 0; j < 16; j++) Mrow[j] = g_M[lane * 16 + j];

    const size_t dbase = ((size_t)c * B_ + (size_t)grp * NSEQ) * SD + lane;

    // scan1: zero-seeded, produce group aggregate
    float p = 0.f;
#pragma unroll 4
    for (int i2 = 0; i2 < NSEQ; i2++) {
        float d = g_d[dbase + (size_t)i2 * SD];
        p = mv16(Mrow, p) + d;
    }
    sAgg[grp * 16 + lane] = p;
    __syncthreads();

    // level-2: warp 0 (both 16-lane halves redundantly) scans 64 aggregates
    if (tid < 32) {
        float L2row[16];
#pragma unroll
        for (int j = 0; j < 16; j++) L2row[j] = g_L2M[lane * 16 + j];
        float q = 0.f;
        for (int g2 = 0; g2 < NG; g2++) {
            if (tid < 16) sGE[g2 * 16 + lane] = q;
            q = mv16(L2row, q) + sAgg[g2 * 16 + lane];
        }
    }
    __syncthreads();

    // rescan seeded with group entry state; p before update = entry of block
    p = sGE[grp * 16 + lane];
#pragma unroll 4
    for (int i2 = 0; i2 < NSEQ; i2++) {
        g_pref[dbase + (size_t)i2 * SD] = p;
        float d = g_d[dbase + (size_t)i2 * SD];
        p = mv16(Mrow, p) + d;
    }
}

// ---------------------------------------------------------------------------
// K3: out[c][b*L+tau] += H[tau] . E[c][b]   (float4 per thread)
// ---------------------------------------------------------------------------
__global__ void __launch_bounds__(256) k3_correct(float* __restrict__ out) {
    const size_t q = (size_t)blockIdx.x * 256 + threadIdx.x;  // < C_*T_/4
    const size_t blk = q >> 5;          // c*B_ + b
    const int tau = (int)(q & 31) << 2; // 0..124

    const float4* s04 = reinterpret_cast<const float4*>(g_pref + blk * SD);
    float s0r[16];
#pragma unroll
    for (int jj = 0; jj < 4; jj++) {
        float4 v = s04[jj];
        s0r[4 * jj + 0] = v.x; s0r[4 * jj + 1] = v.y;
        s0r[4 * jj + 2] = v.z; s0r[4 * jj + 3] = v.w;
    }

    float4* out4 = reinterpret_cast<float4*>(out);
    float4 a = out4[q];
    float accs[4] = {a.x, a.y, a.z, a.w};
#pragma unroll
    for (int r = 0; r < 4; r++) {
        const float4* hr = reinterpret_cast<const float4*>(g_H + (tau + r) * 16);
#pragma unroll
        for (int jj = 0; jj < 4; jj++) {
            float4 h = hr[jj];
            accs[r] = fmaf(h.x, s0r[4 * jj + 0], accs[r]);
            accs[r] = fmaf(h.y, s0r[4 * jj + 1], accs[r]);
            accs[r] = fmaf(h.z, s0r[4 * jj + 2], accs[r]);
            accs[r] = fmaf(h.w, s0r[4 * jj + 3], accs[r]);
        }
    }
    out4[q] = make_float4(accs[0], accs[1], accs[2], accs[3]);
}

// ---------------------------------------------------------------------------
extern "C" void kernel_launch(void* const* d_in, const int* in_sizes, int n_in,
                              void* d_out, int out_size) {
    const float* x   = (const float*)d_in[0];   // [C, T]
    const float* sos = (const float*)d_in[1];   // [8, 6]
    float* out = (float*)d_out;                 // [C, T]

    k0_build<<<1, 256>>>(sos);
    k1_blocks<<<(C_ * B_) / 128, 128>>>(x, sos, out);
    k2_scan<<<C_, 1024>>>();
    k3_correct<<<(C_ * T_ / 4) / 256, 256>>>(out);
}

// round 7
// speedup vs baseline: 4.5874x; 3.6417x over previous
#include <cuda_runtime.h>
#include <cuda_bf16.h>
#include <cstdint>

#define C_   64
#define T_   262144
#define NS   8          // biquad stages
#define SD   16         // state dim (2 per stage, DF2T)
#define L_   128        // samples per block
#define B_   (T_ / L_)  // 2048 blocks per channel
#define NG   64         // groups per channel in scan
#define NSEQ (B_ / NG)  // 32 blocks scanned sequentially per group

#define K3_CTAS    1024
#define K3_THREADS 256
#define K3_NB      ((C_ * B_) / ((K3_CTAS * K3_THREADS) / 32))  // 16 blocks/warp

// Scratch (static device globals; no allocation allowed)
__device__ float g_M[256];                      // A^L  (block step matrix)
__device__ float g_L2M[256];                    // M^NSEQ (level-2 step matrix)
__device__ float g_H[L_ * 16];                  // H[tau][j] = (c^T A^tau)_j
__device__ float g_d[(size_t)C_ * B_ * SD];     // zero-entry exit states per block
__device__ float g_pref[(size_t)C_ * B_ * SD];  // global entry states per block

#define SHFL16(v, j) __shfl_sync(0xffffffffu, (v), (j), 16)

// ---------------------------------------------------------------------------
// K0: build state-space (A, c), H table (doubling), M = A^128, L2M = M^32.
// Entirely in shared memory. One CTA of 256 threads.
// ---------------------------------------------------------------------------
__global__ void k0_build(const float* __restrict__ sos) {
    __shared__ float sA[256];
    __shared__ float sB[256];
    __shared__ float sH[L_ * 16];
    const int tid = threadIdx.x;
    const int i = tid >> 4, j = tid & 15;

    // symbolic build of A (16x16, row-major) and c. Thread tid = input column
    // (0..15 = states, 16 = x). DF2T per stage:
    //   y = b0*u + w1 ; w1' = b1*u - a1*y + w2 ; w2' = b2*u - a2*y
    if (tid < 17) {
        float u = (tid == 16) ? 1.f : 0.f;
        for (int s = 0; s < NS; s++) {
            float B0 = sos[s * 6 + 0], B1 = sos[s * 6 + 1], B2 = sos[s * 6 + 2];
            float A1 = sos[s * 6 + 4], A2 = sos[s * 6 + 5];
            float y  = B0 * u + ((tid == 2 * s) ? 1.f : 0.f);
            float r1 = B1 * u - A1 * y + ((tid == 2 * s + 1) ? 1.f : 0.f);
            float r2 = B2 * u - A2 * y;
            if (tid < 16) {
                sA[(2 * s) * 16 + tid]     = r1;
                sA[(2 * s + 1) * 16 + tid] = r2;
            }
            u = y;
        }
        if (tid < 16) sH[tid] = u;  // H[0] = c
    }
    __syncthreads();

    // interleaved: at loop top sA = A^(2^k). Double H, then square sA.
    for (int k = 0; k <= 6; k++) {
        const int m = 1 << k;
        // H[m + t] = H[t] * sA   for t in [0, m)  (reads rows <m, writes >=m)
        for (int idx = tid; idx < m * 16; idx += 256) {
            const int row = idx >> 4, col = idx & 15;
            float acc = 0.f;
#pragma unroll
            for (int p = 0; p < 16; p++)
                acc = fmaf(sH[row * 16 + p], sA[p * 16 + col], acc);
            sH[(m + row) * 16 + col] = acc;
        }
        __syncthreads();
        // sA = sA * sA
        {
            float acc = 0.f;
#pragma unroll
            for (int p = 0; p < 16; p++)
                acc = fmaf(sA[i * 16 + p], sA[p * 16 + j], acc);
            __syncthreads();
            sB[tid] = acc;
            __syncthreads();
            sA[tid] = sB[tid];
            __syncthreads();
        }
    }
    // sA = A^128 = M
    g_M[tid] = sA[tid];

    // 5 more squarings: M^2 .. M^32
    for (int k = 0; k < 5; k++) {
        float acc = 0.f;
#pragma unroll
        for (int p = 0; p < 16; p++)
            acc = fmaf(sA[i * 16 + p], sA[p * 16 + j], acc);
        __syncthreads();
        sB[tid] = acc;
        __syncthreads();
        sA[tid] = sB[tid];
        __syncthreads();
    }
    g_L2M[tid] = sA[tid];

    for (int idx = tid; idx < L_ * 16; idx += 256) g_H[idx] = sH[idx];
}

// ---------------------------------------------------------------------------
// K1: zero-entry-state cascade per (channel, block), smem-staged coalesced IO.
// CTA = 128 threads = 128 consecutive blocks of one channel. 4 tiles of 32
// samples, sample-major smem layout (row stride 129 floats, conflict-free).
// ---------------------------------------------------------------------------
__global__ void __launch_bounds__(128) k1_blocks(
    const float* __restrict__ x, const float* __restrict__ sos,
    float* __restrict__ out) {
    __shared__ float tile[32 * 129];
    const int tid = threadIdx.x;
    const int c = blockIdx.x >> 4;            // 16 CTAs per channel
    const int blk0 = (blockIdx.x & 15) * 128; // first block of this CTA

    float cb0[NS], cb1[NS], cb2[NS], na1[NS], na2[NS];
#pragma unroll
    for (int s = 0; s < NS; s++) {
        cb0[s] = sos[s * 6 + 0];
        cb1[s] = sos[s * 6 + 1];
        cb2[s] = sos[s * 6 + 2];
        na1[s] = -sos[s * 6 + 4];
        na2[s] = -sos[s * 6 + 5];
    }
    float w1[NS], w2[NS];
#pragma unroll
    for (int s = 0; s < NS; s++) { w1[s] = 0.f; w2[s] = 0.f; }

    const size_t base4 = (size_t)c * (T_ / 4) + (size_t)blk0 * (L_ / 4);
    const float4* xp4 = reinterpret_cast<const float4*>(x) + base4;
    float4* op4 = reinterpret_cast<float4*>(out) + base4;

    for (int t = 0; t < 4; t++) {
        // load: 1024 f4 per tile, coalesced; scatter into sample-major smem
#pragma unroll
        for (int it = 0; it < 8; it++) {
            const int idx = it * 128 + tid;     // 0..1023
            const int bl = idx >> 3;            // local block 0..127
            const int k = idx & 7;              // f4 within tile row of block
            float4 v = xp4[(size_t)bl * 32 + t * 8 + k];
            tile[(4 * k + 0) * 129 + bl] = v.x;
            tile[(4 * k + 1) * 129 + bl] = v.y;
            tile[(4 * k + 2) * 129 + bl] = v.z;
            tile[(4 * k + 3) * 129 + bl] = v.w;
        }
        __syncthreads();
        // compute in place: thread tid = its block's column
#pragma unroll
        for (int s2 = 0; s2 < 32; s2++) {
            float u = tile[s2 * 129 + tid];
#pragma unroll
            for (int s = 0; s < NS; s++) {
                float y = fmaf(cb0[s], u, w1[s]);
                w1[s] = fmaf(cb1[s], u, fmaf(na1[s], y, w2[s]));
                w2[s] = fmaf(cb2[s], u, na2[s] * y);
                u = y;
            }
            tile[s2 * 129 + tid] = u;
        }
        __syncthreads();
        // store: mirror of load, coalesced
#pragma unroll
        for (int it = 0; it < 8; it++) {
            const int idx = it * 128 + tid;
            const int bl = idx >> 3;
            const int k = idx & 7;
            float4 v;
            v.x = tile[(4 * k + 0) * 129 + bl];
            v.y = tile[(4 * k + 1) * 129 + bl];
            v.z = tile[(4 * k + 2) * 129 + bl];
            v.w = tile[(4 * k + 3) * 129 + bl];
            op4[(size_t)bl * 32 + t * 8 + k] = v;
        }
        __syncthreads();
    }

    float* dp = g_d + ((size_t)c * B_ + blk0 + tid) * SD;
#pragma unroll
    for (int s = 0; s < NS; s++) { dp[2 * s] = w1[s]; dp[2 * s + 1] = w2[s]; }
}

// ---------------------------------------------------------------------------
// K2: fused inter-block scan. One CTA per channel, 1024 threads = 64 groups
// of 16 lanes. scan1 (32 steps) -> level-2 scan over 64 aggregates (warp 0,
// M^32) -> rescan seeded with group entry states, writing E to g_pref.
// ---------------------------------------------------------------------------
__device__ __forceinline__ float mv16(const float* Mr, float p) {
    float a0 = 0.f, a1 = 0.f, a2 = 0.f, a3 = 0.f;
#pragma unroll
    for (int j = 0; j < 4; j++)  a0 = fmaf(Mr[j],      SHFL16(p, j),      a0);
#pragma unroll
    for (int j = 0; j < 4; j++)  a1 = fmaf(Mr[j + 4],  SHFL16(p, j + 4),  a1);
#pragma unroll
    for (int j = 0; j < 4; j++)  a2 = fmaf(Mr[j + 8],  SHFL16(p, j + 8),  a2);
#pragma unroll
    for (int j = 0; j < 4; j++)  a3 = fmaf(Mr[j + 12], SHFL16(p, j + 12), a3);
    return (a0 + a1) + (a2 + a3);
}

__global__ void __launch_bounds__(1024) k2_scan(void) {
    __shared__ float sAgg[NG * 16];
    __shared__ float sGE[NG * 16];
    const int tid = threadIdx.x;
    const int lane = tid & 15;
    const int grp = tid >> 4;           // 0..63
    const int c = blockIdx.x;

    float Mrow[16];
#pragma unroll
    for (int j = 0; j < 16; j++) Mrow[j] = g_M[lane * 16 + j];

    const size_t dbase = ((size_t)c * B_ + (size_t)grp * NSEQ) * SD + lane;

    // scan1: zero-seeded, produce group aggregate
    float p = 0.f;
#pragma unroll 4
    for (int i2 = 0; i2 < NSEQ; i2++) {
        float d = g_d[dbase + (size_t)i2 * SD];
        p = mv16(Mrow, p) + d;
    }
    sAgg[grp * 16 + lane] = p;
    __syncthreads();

    // level-2: warp 0 (both 16-lane halves redundantly) scans 64 aggregates
    if (tid < 32) {
        float L2row[16];
#pragma unroll
        for (int j = 0; j < 16; j++) L2row[j] = g_L2M[lane * 16 + j];
        float q = 0.f;
        for (int g2 = 0; g2 < NG; g2++) {
            if (tid < 16) sGE[g2 * 16 + lane] = q;
            q = mv16(L2row, q) + sAgg[g2 * 16 + lane];
        }
    }
    __syncthreads();

    // rescan seeded with group entry state; p before update = entry of block
    p = sGE[grp * 16 + lane];
#pragma unroll 4
    for (int i2 = 0; i2 < NSEQ; i2++) {
        g_pref[dbase + (size_t)i2 * SD] = p;
        float d = g_d[dbase + (size_t)i2 * SD];
        p = mv16(Mrow, p) + d;
    }
}

// ---------------------------------------------------------------------------
// K3: out[c][b*L+tau] += H[tau] . E[c][b].
// Lane owns taus 4*lane..4*lane+3 (H rows in 64 registers, loaded once).
// Warp owns K3_NB consecutive blocks; E loaded as warp-uniform broadcast
// float4s (1 wavefront each); out RMW is a fully-coalesced 512B/warp float4.
// ---------------------------------------------------------------------------
__global__ void __launch_bounds__(K3_THREADS) k3_correct(float* __restrict__ out) {
    const int lane = threadIdx.x & 31;
    const int gwarp = (blockIdx.x * K3_THREADS + threadIdx.x) >> 5;

    // H rows for this lane's 4 taus -> registers (one-time, per-lane scattered)
    float Hreg[4][16];
#pragma unroll
    for (int r = 0; r < 4; r++) {
        const float4* hp = reinterpret_cast<const float4*>(g_H + (4 * lane + r) * 16);
#pragma unroll
        for (int jj = 0; jj < 4; jj++) {
            float4 h = hp[jj];
            Hreg[r][4 * jj + 0] = h.x; Hreg[r][4 * jj + 1] = h.y;
            Hreg[r][4 * jj + 2] = h.z; Hreg[r][4 * jj + 3] = h.w;
        }
    }

    const size_t blk0 = (size_t)gwarp * K3_NB;
    float4* out4 = reinterpret_cast<float4*>(out);

#pragma unroll 1
    for (int i = 0; i < K3_NB; i++) {
        const size_t blk = blk0 + i;
        // E: warp-uniform broadcast loads
        const float4* e4 = reinterpret_cast<const float4*>(g_pref + blk * SD);
        float E[16];
#pragma unroll
        for (int jj = 0; jj < 4; jj++) {
            float4 v = e4[jj];
            E[4 * jj + 0] = v.x; E[4 * jj + 1] = v.y;
            E[4 * jj + 2] = v.z; E[4 * jj + 3] = v.w;
        }
        float4* op = out4 + blk * 32 + lane;
        float4 a = *op;
        float accs[4] = {a.x, a.y, a.z, a.w};
#pragma unroll
        for (int r = 0; r < 4; r++)
#pragma unroll
            for (int j = 0; j < 16; j++)
                accs[r] = fmaf(Hreg[r][j], E[j], accs[r]);
        *op = make_float4(accs[0], accs[1], accs[2], accs[3]);
    }
}

// ---------------------------------------------------------------------------
extern "C" void kernel_launch(void* const* d_in, const int* in_sizes, int n_in,
                              void* d_out, int out_size) {
    const float* x   = (const float*)d_in[0];   // [C, T]
    const float* sos = (const float*)d_in[1];   // [8, 6]
    float* out = (float*)d_out;                 // [C, T]

    k0_build<<<1, 256>>>(sos);
    k1_blocks<<<(C_ * B_) / 128, 128>>>(x, sos, out);
    k2_scan<<<C_, 1024>>>();
    k3_correct<<<K3_CTAS, K3_THREADS>>>(out);
}

// round 8
// speedup vs baseline: 4.6576x; 1.0153x over previous
#include <cuda_runtime.h>
#include <cuda_bf16.h>
#include <cstdint>

#define C_   64
#define T_   262144
#define NS   8          // biquad stages
#define SD   16         // state dim (2 per stage, DF2T)
#define L_   128        // samples per block
#define B_   (T_ / L_)  // 2048 blocks per channel
#define NG   64         // groups per channel in scan
#define NSEQ (B_ / NG)  // 32 blocks scanned sequentially per group

#define K3_CTAS    2048
#define K3_THREADS 256
#define K3_NB      16   // blocks (half-blocks) per warp

// Scratch (static device globals; no allocation allowed)
__device__ float g_M[256];                      // A^L  (block step matrix)
__device__ float g_L2M[256];                    // M^NSEQ (level-2 step matrix)
__device__ float g_H[L_ * 16];                  // H[tau][j] = (c^T A^tau)_j
__device__ float g_d[(size_t)C_ * B_ * SD];     // zero-entry exit states per block
__device__ float g_pref[(size_t)C_ * B_ * SD];  // global entry states per block

#define SHFL16(v, j) __shfl_sync(0xffffffffu, (v), (j), 16)

// ---- packed f32x2 helpers (sm_103a) ---------------------------------------
__device__ __forceinline__ unsigned long long pk2(float lo, float hi) {
    unsigned long long r;
    asm("mov.b64 %0, {%1, %2};" : "=l"(r)
        : "r"(__float_as_uint(lo)), "r"(__float_as_uint(hi)));
    return r;
}
__device__ __forceinline__ void upk2(unsigned long long v, float& lo, float& hi) {
    unsigned int a, b;
    asm("mov.b64 {%0, %1}, %2;" : "=r"(a), "=r"(b) : "l"(v));
    lo = __uint_as_float(a); hi = __uint_as_float(b);
}
__device__ __forceinline__ unsigned long long ffma2(
    unsigned long long a, unsigned long long b, unsigned long long c) {
    unsigned long long d;
    asm("fma.rn.f32x2 %0, %1, %2, %3;" : "=l"(d) : "l"(a), "l"(b), "l"(c));
    return d;
}
__device__ __forceinline__ unsigned long long fmul2(
    unsigned long long a, unsigned long long b) {
    unsigned long long d;
    asm("mul.rn.f32x2 %0, %1, %2;" : "=l"(d) : "l"(a), "l"(b));
    return d;
}

// ---------------------------------------------------------------------------
// K0: build state-space (A, c), H table (doubling), M = A^128, L2M = M^32.
// Entirely in shared memory. One CTA of 256 threads.
// ---------------------------------------------------------------------------
__global__ void k0_build(const float* __restrict__ sos) {
    __shared__ float sA[256];
    __shared__ float sB[256];
    __shared__ float sH[L_ * 16];
    const int tid = threadIdx.x;
    const int i = tid >> 4, j = tid & 15;

    if (tid < 17) {
        float u = (tid == 16) ? 1.f : 0.f;
        for (int s = 0; s < NS; s++) {
            float B0 = sos[s * 6 + 0], B1 = sos[s * 6 + 1], B2 = sos[s * 6 + 2];
            float A1 = sos[s * 6 + 4], A2 = sos[s * 6 + 5];
            float y  = B0 * u + ((tid == 2 * s) ? 1.f : 0.f);
            float r1 = B1 * u - A1 * y + ((tid == 2 * s + 1) ? 1.f : 0.f);
            float r2 = B2 * u - A2 * y;
            if (tid < 16) {
                sA[(2 * s) * 16 + tid]     = r1;
                sA[(2 * s + 1) * 16 + tid] = r2;
            }
            u = y;
        }
        if (tid < 16) sH[tid] = u;  // H[0] = c
    }
    __syncthreads();

    for (int k = 0; k <= 6; k++) {
        const int m = 1 << k;
        for (int idx = tid; idx < m * 16; idx += 256) {
            const int row = idx >> 4, col = idx & 15;
            float acc = 0.f;
#pragma unroll
            for (int p = 0; p < 16; p++)
                acc = fmaf(sH[row * 16 + p], sA[p * 16 + col], acc);
            sH[(m + row) * 16 + col] = acc;
        }
        __syncthreads();
        {
            float acc = 0.f;
#pragma unroll
            for (int p = 0; p < 16; p++)
                acc = fmaf(sA[i * 16 + p], sA[p * 16 + j], acc);
            __syncthreads();
            sB[tid] = acc;
            __syncthreads();
            sA[tid] = sB[tid];
            __syncthreads();
        }
    }
    g_M[tid] = sA[tid];

    for (int k = 0; k < 5; k++) {
        float acc = 0.f;
#pragma unroll
        for (int p = 0; p < 16; p++)
            acc = fmaf(sA[i * 16 + p], sA[p * 16 + j], acc);
        __syncthreads();
        sB[tid] = acc;
        __syncthreads();
        sA[tid] = sB[tid];
        __syncthreads();
    }
    g_L2M[tid] = sA[tid];

    for (int idx = tid; idx < L_ * 16; idx += 256) g_H[idx] = sH[idx];
}

// ---------------------------------------------------------------------------
// K1: zero-entry-state cascade, f32x2-packed: each thread runs TWO blocks
// (tid and tid+128) through the cascade with packed FFMA2. CTA covers 256
// consecutive blocks of one channel; smem tile 32 samples x 257 (conflict-
// free staging).
// ---------------------------------------------------------------------------
__global__ void __launch_bounds__(128) k1_blocks(
    const float* __restrict__ x, const float* __restrict__ sos,
    float* __restrict__ out) {
    __shared__ float tile[32 * 257];
    const int tid = threadIdx.x;
    const int c = blockIdx.x >> 3;            // 8 CTAs per channel
    const int blk0 = (blockIdx.x & 7) * 256;  // first of 256 blocks

    typedef unsigned long long u64;
    u64 cb0[NS], cb1[NS], cb2[NS], na1[NS], na2[NS];
#pragma unroll
    for (int s = 0; s < NS; s++) {
        float b0 = sos[s * 6 + 0], b1 = sos[s * 6 + 1], b2 = sos[s * 6 + 2];
        float a1 = -sos[s * 6 + 4], a2 = -sos[s * 6 + 5];
        cb0[s] = pk2(b0, b0); cb1[s] = pk2(b1, b1); cb2[s] = pk2(b2, b2);
        na1[s] = pk2(a1, a1); na2[s] = pk2(a2, a2);
    }
    u64 w1[NS], w2[NS];
    const u64 z2 = pk2(0.f, 0.f);
#pragma unroll
    for (int s = 0; s < NS; s++) { w1[s] = z2; w2[s] = z2; }

    const size_t base4 = (size_t)c * (T_ / 4) + (size_t)blk0 * (L_ / 4);
    const float4* xp4 = reinterpret_cast<const float4*>(x) + base4;
    float4* op4 = reinterpret_cast<float4*>(out) + base4;

    for (int t = 0; t < 4; t++) {
        // load: 2048 f4 per tile, coalesced; scatter to sample-major smem
#pragma unroll
        for (int it = 0; it < 16; it++) {
            const int idx = it * 128 + tid;     // 0..2047
            const int bl = idx >> 3;            // local block 0..255
            const int k = idx & 7;
            float4 v = xp4[(size_t)bl * 32 + t * 8 + k];
            tile[(4 * k + 0) * 257 + bl] = v.x;
            tile[(4 * k + 1) * 257 + bl] = v.y;
            tile[(4 * k + 2) * 257 + bl] = v.z;
            tile[(4 * k + 3) * 257 + bl] = v.w;
        }
        __syncthreads();
        // compute: thread owns columns tid and tid+128, packed
#pragma unroll
        for (int s2 = 0; s2 < 32; s2++) {
            u64 u = pk2(tile[s2 * 257 + tid], tile[s2 * 257 + 128 + tid]);
#pragma unroll
            for (int s = 0; s < NS; s++) {
                u64 y = ffma2(cb0[s], u, w1[s]);
                w1[s] = ffma2(cb1[s], u, ffma2(na1[s], y, w2[s]));
                w2[s] = ffma2(cb2[s], u, fmul2(na2[s], y));
                u = y;
            }
            float lo, hi; upk2(u, lo, hi);
            tile[s2 * 257 + tid] = lo;
            tile[s2 * 257 + 128 + tid] = hi;
        }
        __syncthreads();
        // store: mirror of load
#pragma unroll
        for (int it = 0; it < 16; it++) {
            const int idx = it * 128 + tid;
            const int bl = idx >> 3;
            const int k = idx & 7;
            float4 v;
            v.x = tile[(4 * k + 0) * 257 + bl];
            v.y = tile[(4 * k + 1) * 257 + bl];
            v.z = tile[(4 * k + 2) * 257 + bl];
            v.w = tile[(4 * k + 3) * 257 + bl];
            op4[(size_t)bl * 32 + t * 8 + k] = v;
        }
        __syncthreads();
    }

    // exit states for both blocks
    float* dlo = g_d + ((size_t)c * B_ + blk0 + tid) * SD;
    float* dhi = g_d + ((size_t)c * B_ + blk0 + 128 + tid) * SD;
#pragma unroll
    for (int s = 0; s < NS; s++) {
        float lo, hi;
        upk2(w1[s], lo, hi); dlo[2 * s] = lo; dhi[2 * s] = hi;
        upk2(w2[s], lo, hi); dlo[2 * s + 1] = lo; dhi[2 * s + 1] = hi;
    }
}

// ---------------------------------------------------------------------------
// K2: fused inter-block scan. One CTA per channel, 1024 threads = 64 groups
// of 16 lanes. scan1 -> level-2 scan (warp 0, M^32) -> rescan, E to g_pref.
// ---------------------------------------------------------------------------
__device__ __forceinline__ float mv16(const float* Mr, float p) {
    float a0 = 0.f, a1 = 0.f, a2 = 0.f, a3 = 0.f;
#pragma unroll
    for (int j = 0; j < 4; j++)  a0 = fmaf(Mr[j],      SHFL16(p, j),      a0);
#pragma unroll
    for (int j = 0; j < 4; j++)  a1 = fmaf(Mr[j + 4],  SHFL16(p, j + 4),  a1);
#pragma unroll
    for (int j = 0; j < 4; j++)  a2 = fmaf(Mr[j + 8],  SHFL16(p, j + 8),  a2);
#pragma unroll
    for (int j = 0; j < 4; j++)  a3 = fmaf(Mr[j + 12], SHFL16(p, j + 12), a3);
    return (a0 + a1) + (a2 + a3);
}

__global__ void __launch_bounds__(1024) k2_scan(void) {
    __shared__ float sAgg[NG * 16];
    __shared__ float sGE[NG * 16];
    const int tid = threadIdx.x;
    const int lane = tid & 15;
    const int grp = tid >> 4;
    const int c = blockIdx.x;

    float Mrow[16];
#pragma unroll
    for (int j = 0; j < 16; j++) Mrow[j] = g_M[lane * 16 + j];

    const size_t dbase = ((size_t)c * B_ + (size_t)grp * NSEQ) * SD + lane;

    float p = 0.f;
#pragma unroll 4
    for (int i2 = 0; i2 < NSEQ; i2++) {
        float d = g_d[dbase + (size_t)i2 * SD];
        p = mv16(Mrow, p) + d;
    }
    sAgg[grp * 16 + lane] = p;
    __syncthreads();

    if (tid < 32) {
        float L2row[16];
#pragma unroll
        for (int j = 0; j < 16; j++) L2row[j] = g_L2M[lane * 16 + j];
        float q = 0.f;
        for (int g2 = 0; g2 < NG; g2++) {
            if (tid < 16) sGE[g2 * 16 + lane] = q;
            q = mv16(L2row, q) + sAgg[g2 * 16 + lane];
        }
    }
    __syncthreads();

    p = sGE[grp * 16 + lane];
#pragma unroll 4
    for (int i2 = 0; i2 < NSEQ; i2++) {
        g_pref[dbase + (size_t)i2 * SD] = p;
        float d = g_d[dbase + (size_t)i2 * SD];
        p = mv16(Mrow, p) + d;
    }
}

// ---------------------------------------------------------------------------
// K3: out[c][b*L+tau] += H[tau] . E[c][b].
// Each warp handles HALF a block (64 taus): lane owns taus h*64 + 2*lane
// and +1 -> Hreg[2][16] (32 regs). out RMW is float2 per lane, 256B/warp
// coalesced. h fixed per warp so Hreg loads once.
// ---------------------------------------------------------------------------
__global__ void __launch_bounds__(K3_THREADS) k3_correct(float* __restrict__ out) {
    const int lane = threadIdx.x & 31;
    const int gwarp = (blockIdx.x * K3_THREADS + threadIdx.x) >> 5;  // 0..16383
    const int h = gwarp >> 13;                 // 0 or 1 (half of block)
    const int wseq = gwarp & 8191;             // 8192 warps per half
    const int tau0 = h * 64 + 2 * lane;

    float Hreg[2][16];
#pragma unroll
    for (int r = 0; r < 2; r++) {
        const float4* hp = reinterpret_cast<const float4*>(g_H + (tau0 + r) * 16);
#pragma unroll
        for (int jj = 0; jj < 4; jj++) {
            float4 hv = hp[jj];
            Hreg[r][4 * jj + 0] = hv.x; Hreg[r][4 * jj + 1] = hv.y;
            Hreg[r][4 * jj + 2] = hv.z; Hreg[r][4 * jj + 3] = hv.w;
        }
    }

    const size_t blk0 = (size_t)wseq * K3_NB;
    float2* out2 = reinterpret_cast<float2*>(out);

#pragma unroll 1
    for (int i = 0; i < K3_NB; i++) {
        const size_t blk = blk0 + i;
        const float4* e4 = reinterpret_cast<const float4*>(g_pref + blk * SD);
        float E[16];
#pragma unroll
        for (int jj = 0; jj < 4; jj++) {
            float4 v = e4[jj];
            E[4 * jj + 0] = v.x; E[4 * jj + 1] = v.y;
            E[4 * jj + 2] = v.z; E[4 * jj + 3] = v.w;
        }
        float2* op = out2 + blk * 64 + h * 32 + lane;
        float2 a = *op;
#pragma unroll
        for (int j = 0; j < 16; j++) {
            a.x = fmaf(Hreg[0][j], E[j], a.x);
            a.y = fmaf(Hreg[1][j], E[j], a.y);
        }
        *op = a;
    }
}

// ---------------------------------------------------------------------------
extern "C" void kernel_launch(void* const* d_in, const int* in_sizes, int n_in,
                              void* d_out, int out_size) {
    const float* x   = (const float*)d_in[0];   // [C, T]
    const float* sos = (const float*)d_in[1];   // [8, 6]
    float* out = (float*)d_out;                 // [C, T]

    k0_build<<<1, 256>>>(sos);
    k1_blocks<<<(C_ * B_) / 256, 128>>>(x, sos, out);
    k2_scan<<<C_, 1024>>>();
    k3_correct<<<K3_CTAS, K3_THREADS>>>(out);
}

// round 9
// speedup vs baseline: 5.5815x; 1.1984x over previous
#include <cuda_runtime.h>
#include <cuda_bf16.h>
#include <cstdint>

#define C_   64
#define T_   262144
#define NS   8          // biquad stages
#define SD   16         // state dim (2 per stage, DF2T)
#define L_   128        // samples per block
#define B_   (T_ / L_)  // 2048 blocks per channel
#define NG   64         // groups per channel in scan
#define NSEQ (B_ / NG)  // 32 blocks scanned sequentially per group

// Scratch (static device globals; no allocation allowed)
__device__ float g_M[256];                      // A^L  (block step matrix)
__device__ float g_L2M[256];                    // M^NSEQ (level-2 step matrix)
__device__ float g_F[L_ * 16];                  // F[tau][j] = (A^(L-1-tau) B)_j
__device__ float g_d[(size_t)C_ * B_ * SD];     // zero-entry exit states per block
__device__ float g_pref[(size_t)C_ * B_ * SD];  // global entry states per block

#define SHFL16(v, j) __shfl_sync(0xffffffffu, (v), (j), 16)

// ---------------------------------------------------------------------------
// K0: build state-space (A, B), F table (doubling: G[t] = A^t B, F[tau] =
// G[L-1-tau]), M = A^128, L2M = M^32. All in shared memory. One CTA.
// ---------------------------------------------------------------------------
__global__ void k0_build(const float* __restrict__ sos) {
    __shared__ float sA[256];
    __shared__ float sB[256];
    __shared__ float sG[L_ * 16];   // G[t][j] = (A^t B)_j
    const int tid = threadIdx.x;
    const int i = tid >> 4, j = tid & 15;

    // symbolic build of A (16x16, row-major) and B (input column). Thread tid
    // = input column (0..15 = states, 16 = x). DF2T per stage:
    //   y = b0*u + w1 ; w1' = b1*u - a1*y + w2 ; w2' = b2*u - a2*y
    if (tid < 17) {
        float u = (tid == 16) ? 1.f : 0.f;
        for (int s = 0; s < NS; s++) {
            float B0 = sos[s * 6 + 0], B1 = sos[s * 6 + 1], B2 = sos[s * 6 + 2];
            float A1 = sos[s * 6 + 4], A2 = sos[s * 6 + 5];
            float y  = B0 * u + ((tid == 2 * s) ? 1.f : 0.f);
            float r1 = B1 * u - A1 * y + ((tid == 2 * s + 1) ? 1.f : 0.f);
            float r2 = B2 * u - A2 * y;
            if (tid < 16) {
                sA[(2 * s) * 16 + tid]     = r1;
                sA[(2 * s + 1) * 16 + tid] = r2;
            }
            if (tid == 16) {            // B vector = G[0]
                sG[2 * s]     = r1;
                sG[2 * s + 1] = r2;
            }
            u = y;
        }
    }
    __syncthreads();

    // doubling: at loop top sA = A^(2^k), sG holds G[0..m). Extend G, square A.
    for (int k = 0; k <= 6; k++) {
        const int m = 1 << k;
        // G[m + t] = sA * G[t]  for t in [0, m)   (reads rows <m, writes >=m)
        for (int idx = tid; idx < m * 16; idx += 256) {
            const int t = idx >> 4, comp = idx & 15;
            float acc = 0.f;
#pragma unroll
            for (int p = 0; p < 16; p++)
                acc = fmaf(sA[comp * 16 + p], sG[t * 16 + p], acc);
            sG[(m + t) * 16 + comp] = acc;
        }
        __syncthreads();
        // sA = sA * sA
        {
            float acc = 0.f;
#pragma unroll
            for (int p = 0; p < 16; p++)
                acc = fmaf(sA[i * 16 + p], sA[p * 16 + j], acc);
            __syncthreads();
            sB[tid] = acc;
            __syncthreads();
            sA[tid] = sB[tid];
            __syncthreads();
        }
    }
    // sA = A^128 = M
    g_M[tid] = sA[tid];

    // 5 more squarings: M^32
    for (int k = 0; k < 5; k++) {
        float acc = 0.f;
#pragma unroll
        for (int p = 0; p < 16; p++)
            acc = fmaf(sA[i * 16 + p], sA[p * 16 + j], acc);
        __syncthreads();
        sB[tid] = acc;
        __syncthreads();
        sA[tid] = sB[tid];
        __syncthreads();
    }
    g_L2M[tid] = sA[tid];

    // F[tau] = G[L-1-tau]
    for (int idx = tid; idx < L_ * 16; idx += 256) {
        const int tau = idx >> 4, comp = idx & 15;
        g_F[idx] = sG[(L_ - 1 - tau) * 16 + comp];
    }
}

// ---------------------------------------------------------------------------
// K1a: per-block exit state d = sum_tau F[tau] * x[tau]. Pure dot products
// (no serial chain). CTA = 128 threads = 128 consecutive blocks; smem-staged
// coalesced x loads, F broadcast from smem.
// ---------------------------------------------------------------------------
__global__ void __launch_bounds__(128) k1a_dstates(const float* __restrict__ x) {
    __shared__ float sF[L_ * 16];
    __shared__ float tile[32 * 129];
    const int tid = threadIdx.x;
    const int c = blockIdx.x >> 4;            // 16 CTAs per channel
    const int blk0 = (blockIdx.x & 15) * 128;

    for (int idx = tid; idx < L_ * 16; idx += 128) sF[idx] = g_F[idx];

    float acc[16];
#pragma unroll
    for (int j = 0; j < 16; j++) acc[j] = 0.f;

    const size_t base4 = (size_t)c * (T_ / 4) + (size_t)blk0 * (L_ / 4);
    const float4* xp4 = reinterpret_cast<const float4*>(x) + base4;
    __syncthreads();

    for (int t = 0; t < 4; t++) {
        // load tile: coalesced gmem -> sample-major smem
#pragma unroll
        for (int it = 0; it < 8; it++) {
            const int idx = it * 128 + tid;
            const int bl = idx >> 3;
            const int k = idx & 7;
            float4 v = xp4[(size_t)bl * 32 + t * 8 + k];
            tile[(4 * k + 0) * 129 + bl] = v.x;
            tile[(4 * k + 1) * 129 + bl] = v.y;
            tile[(4 * k + 2) * 129 + bl] = v.z;
            tile[(4 * k + 3) * 129 + bl] = v.w;
        }
        __syncthreads();
#pragma unroll
        for (int s2 = 0; s2 < 32; s2++) {
            const float u = tile[s2 * 129 + tid];
            const float4* fr = reinterpret_cast<const float4*>(sF + (t * 32 + s2) * 16);
#pragma unroll
            for (int jj = 0; jj < 4; jj++) {
                float4 f = fr[jj];
                acc[4 * jj + 0] = fmaf(f.x, u, acc[4 * jj + 0]);
                acc[4 * jj + 1] = fmaf(f.y, u, acc[4 * jj + 1]);
                acc[4 * jj + 2] = fmaf(f.z, u, acc[4 * jj + 2]);
                acc[4 * jj + 3] = fmaf(f.w, u, acc[4 * jj + 3]);
            }
        }
        __syncthreads();
    }

    float* dp = g_d + ((size_t)c * B_ + blk0 + tid) * SD;
#pragma unroll
    for (int j = 0; j < 16; j++) dp[j] = acc[j];
}

// ---------------------------------------------------------------------------
// K2: fused inter-block scan. One CTA per channel, 1024 threads = 64 groups
// of 16 lanes. scan1 -> level-2 scan (warp 0, M^32) -> rescan, E to g_pref.
// ---------------------------------------------------------------------------
__device__ __forceinline__ float mv16(const float* Mr, float p) {
    float a0 = 0.f, a1 = 0.f, a2 = 0.f, a3 = 0.f;
#pragma unroll
    for (int j = 0; j < 4; j++)  a0 = fmaf(Mr[j],      SHFL16(p, j),      a0);
#pragma unroll
    for (int j = 0; j < 4; j++)  a1 = fmaf(Mr[j + 4],  SHFL16(p, j + 4),  a1);
#pragma unroll
    for (int j = 0; j < 4; j++)  a2 = fmaf(Mr[j + 8],  SHFL16(p, j + 8),  a2);
#pragma unroll
    for (int j = 0; j < 4; j++)  a3 = fmaf(Mr[j + 12], SHFL16(p, j + 12), a3);
    return (a0 + a1) + (a2 + a3);
}

__global__ void __launch_bounds__(1024) k2_scan(void) {
    __shared__ float sAgg[NG * 16];
    __shared__ float sGE[NG * 16];
    const int tid = threadIdx.x;
    const int lane = tid & 15;
    const int grp = tid >> 4;
    const int c = blockIdx.x;

    float Mrow[16];
#pragma unroll
    for (int j = 0; j < 16; j++) Mrow[j] = g_M[lane * 16 + j];

    const size_t dbase = ((size_t)c * B_ + (size_t)grp * NSEQ) * SD + lane;

    float p = 0.f;
#pragma unroll 4
    for (int i2 = 0; i2 < NSEQ; i2++) {
        float d = g_d[dbase + (size_t)i2 * SD];
        p = mv16(Mrow, p) + d;
    }
    sAgg[grp * 16 + lane] = p;
    __syncthreads();

    if (tid < 32) {
        float L2row[16];
#pragma unroll
        for (int j = 0; j < 16; j++) L2row[j] = g_L2M[lane * 16 + j];
        float q = 0.f;
        for (int g2 = 0; g2 < NG; g2++) {
            if (tid < 16) sGE[g2 * 16 + lane] = q;
            q = mv16(L2row, q) + sAgg[g2 * 16 + lane];
        }
    }
    __syncthreads();

    p = sGE[grp * 16 + lane];
#pragma unroll 4
    for (int i2 = 0; i2 < NSEQ; i2++) {
        g_pref[dbase + (size_t)i2 * SD] = p;
        float d = g_d[dbase + (size_t)i2 * SD];
        p = mv16(Mrow, p) + d;
    }
}

// ---------------------------------------------------------------------------
// K1c: exact cascade per block, seeded with the true entry state E. Writes
// the final output directly (no correction pass). Same smem staging as k1a.
// ---------------------------------------------------------------------------
__global__ void __launch_bounds__(128) k1c_final(
    const float* __restrict__ x, const float* __restrict__ sos,
    float* __restrict__ out) {
    __shared__ float tile[32 * 129];
    const int tid = threadIdx.x;
    const int c = blockIdx.x >> 4;
    const int blk0 = (blockIdx.x & 15) * 128;

    float cb0[NS], cb1[NS], cb2[NS], na1[NS], na2[NS];
#pragma unroll
    for (int s = 0; s < NS; s++) {
        cb0[s] = sos[s * 6 + 0];
        cb1[s] = sos[s * 6 + 1];
        cb2[s] = sos[s * 6 + 2];
        na1[s] = -sos[s * 6 + 4];
        na2[s] = -sos[s * 6 + 5];
    }
    // seed with entry state E (per-thread 64B, one-time)
    float w1[NS], w2[NS];
    {
        const float* ep = g_pref + ((size_t)c * B_ + blk0 + tid) * SD;
#pragma unroll
        for (int s = 0; s < NS; s++) { w1[s] = ep[2 * s]; w2[s] = ep[2 * s + 1]; }
    }

    const size_t base4 = (size_t)c * (T_ / 4) + (size_t)blk0 * (L_ / 4);
    const float4* xp4 = reinterpret_cast<const float4*>(x) + base4;
    float4* op4 = reinterpret_cast<float4*>(out) + base4;

    for (int t = 0; t < 4; t++) {
#pragma unroll
        for (int it = 0; it < 8; it++) {
            const int idx = it * 128 + tid;
            const int bl = idx >> 3;
            const int k = idx & 7;
            float4 v = xp4[(size_t)bl * 32 + t * 8 + k];
            tile[(4 * k + 0) * 129 + bl] = v.x;
            tile[(4 * k + 1) * 129 + bl] = v.y;
            tile[(4 * k + 2) * 129 + bl] = v.z;
            tile[(4 * k + 3) * 129 + bl] = v.w;
        }
        __syncthreads();
#pragma unroll
        for (int s2 = 0; s2 < 32; s2++) {
            float u = tile[s2 * 129 + tid];
#pragma unroll
            for (int s = 0; s < NS; s++) {
                float y = fmaf(cb0[s], u, w1[s]);
                w1[s] = fmaf(cb1[s], u, fmaf(na1[s], y, w2[s]));
                w2[s] = fmaf(cb2[s], u, na2[s] * y);
                u = y;
            }
            tile[s2 * 129 + tid] = u;
        }
        __syncthreads();
#pragma unroll
        for (int it = 0; it < 8; it++) {
            const int idx = it * 128 + tid;
            const int bl = idx >> 3;
            const int k = idx & 7;
            float4 v;
            v.x = tile[(4 * k + 0) * 129 + bl];
            v.y = tile[(4 * k + 1) * 129 + bl];
            v.z = tile[(4 * k + 2) * 129 + bl];
            v.w = tile[(4 * k + 3) * 129 + bl];
            op4[(size_t)bl * 32 + t * 8 + k] = v;
        }
        __syncthreads();
    }
}

// ---------------------------------------------------------------------------
extern "C" void kernel_launch(void* const* d_in, const int* in_sizes, int n_in,
                              void* d_out, int out_size) {
    const float* x   = (const float*)d_in[0];   // [C, T]
    const float* sos = (const float*)d_in[1];   // [8, 6]
    float* out = (float*)d_out;                 // [C, T]

    k0_build<<<1, 256>>>(sos);
    k1a_dstates<<<(C_ * B_) / 128, 128>>>(x);
    k2_scan<<<C_, 1024>>>();
    k1c_final<<<(C_ * B_) / 128, 128>>>(x, sos, out);
}